// round 5
// baseline (speedup 1.0000x reference)
#include <cuda_runtime.h>
#include <cstdint>

// ===========================================================================
// VQ-VAE quantizer via warp-level 3xTF32 mma.sync (m16n8k8) argmin-GEMM.
// (tcgen05 unavailable: harness compiles PTX at compute_103, no 'a' features)
//
//   x [4,64,32,32,32] fp32, weight [512,64] fp32
//   out: quantized_st (8.4M), embed_idx (131072, as float), latent_loss (1)
//
// score_j = wsq_j - 2*dot(x,w_j); dot via 3xTF32 (hi*hi + hi*lo + lo*hi).
// Block: 256 thr / 8 warps, 256 positions (warp = 2 M-tiles of 16),
// codes in 2 smem chunks of 256 (B pre-swizzled to fragment order: 1 LDS.64
// per B-frag). 4 acc chains per warp hide HMMA latency.
// ===========================================================================

static constexpr int C = 64, E = 512, S = 32768;

__device__ float g_partials[512];

// ---- smem layout (bytes) ----------------------------------------------------
static constexpr int OFF_B   = 0;                   // 2 passes x 16384 floats
static constexpr int OFF_XS  = 131072;              // 256 x 68 fp32
static constexpr int OFF_WSQ = OFF_XS + 256 * 68 * 4;   // 512 fp32
static constexpr int OFF_IDX = OFF_WSQ + 2048;          // 256 int
static constexpr int OFF_RED = OFF_IDX + 1024;          // 256 fp32
static constexpr int SMEM_TOTAL = OFF_RED + 1024;       // 204800

__device__ __forceinline__ uint32_t smem_to_u32(const void* p) {
    uint32_t a;
    asm("{ .reg .u64 t; cvta.to.shared.u64 t, %1; cvt.u32.u64 %0, t; }"
        : "=r"(a) : "l"(p));
    return a;
}
__device__ __forceinline__ uint32_t f2tf32(float v) {
    uint32_t r;
    asm("cvt.rna.tf32.f32 %0, %1;" : "=r"(r) : "f"(v));
    return r;
}

#define LDS64(r0, r1, addr) \
    asm volatile("ld.shared.v2.b32 {%0,%1}, [%2];" \
                 : "=r"(r0), "=r"(r1) : "r"(addr))

#define MMA_TF32(acc, a, b0, b1) \
    asm volatile("mma.sync.aligned.m16n8k8.row.col.f32.tf32.tf32.f32 " \
                 "{%0,%1,%2,%3}, {%4,%5,%6,%7}, {%8,%9}, {%0,%1,%2,%3};" \
                 : "+f"((acc)[0]), "+f"((acc)[1]), "+f"((acc)[2]), "+f"((acc)[3]) \
                 : "r"((a)[0]), "r"((a)[1]), "r"((a)[2]), "r"((a)[3]), \
                   "r"(b0), "r"(b1))

// ===========================================================================
__global__ void __launch_bounds__(256, 1) vq_hmma_kernel(
    const float* __restrict__ x, const float* __restrict__ w,
    float* __restrict__ out_q, float* __restrict__ out_idx)
{
    extern __shared__ char smem[];
    const uint32_t smem_u = smem_to_u32(smem);
    float* xs    = (float*)(smem + OFF_XS);    // [256][68]
    float* wsqs  = (float*)(smem + OFF_WSQ);   // [512]
    int*   idxb  = (int*)  (smem + OFF_IDX);   // [256]
    float* redb  = (float*)(smem + OFF_RED);   // [256]

    const int tid = threadIdx.x;
    const int l   = tid & 31;
    const int wid = tid >> 5;
    const int wbase = wid * 32;                // warp's first position (local)

    const int p0 = blockIdx.x * 256;
    const int b  = p0 >> 15;
    const int s0 = p0 & (S - 1);
    const float* xb = x + (size_t)b * C * S + s0;

    // ---- x tile -> smem (coalesced gmem) ----
    for (int e = tid; e < 256 * 64; e += 256) {
        const int k  = e >> 8;
        const int pl = e & 255;
        xs[pl * 68 + k] = xb[(size_t)k * S + pl];
    }
    // ---- wsq ----
    for (int j = tid; j < E; j += 256) {
        float s = 0.f;
        #pragma unroll
        for (int c = 0; c < C; ++c) {
            const float v = w[j * C + c];
            s = fmaf(v, v, s);
        }
        wsqs[j] = s;
    }
    __syncthreads();

    // ---- A fragments (held in registers across both chunks) ----
    // m16n8k8 tf32: a0=A[l/4][l%4], a1=A[l/4+8][l%4], a2=A[l/4][l%4+4], a3=A[l/4+8][l%4+4]
    uint32_t Ahi0[8][4], Alo0[8][4], Ahi1[8][4], Alo1[8][4];
    {
        const int r = wbase + (l >> 2);
        const int kb = (l & 3);
        #pragma unroll
        for (int ks = 0; ks < 8; ++ks) {
            #pragma unroll
            for (int i = 0; i < 4; ++i) {
                const int rr = r + ((i & 1) << 3);
                const int kk = ks * 8 + kb + ((i >> 1) << 2);
                float raw0 = xs[rr * 68 + kk];            // Mt0
                float raw1 = xs[(rr + 16) * 68 + kk];     // Mt1
                Ahi0[ks][i] = f2tf32(raw0);
                Alo0[ks][i] = f2tf32(raw0 - __uint_as_float(Ahi0[ks][i]));
                Ahi1[ks][i] = f2tf32(raw1);
                Alo1[ks][i] = f2tf32(raw1 - __uint_as_float(Ahi1[ks][i]));
            }
        }
    }

    float best0 = 3.4e38f, best1 = 3.4e38f, best2 = 3.4e38f, best3 = 3.4e38f;
    int   bidx0 = 0, bidx1 = 0, bidx2 = 0, bidx3 = 0;

    const uint32_t bbase = smem_u + OFF_B;
    const uint32_t loff  = (uint32_t)(((l >> 2) << 5) + ((l & 3) << 3)); // lane byte offset

    #pragma unroll 1
    for (int chunk = 0; chunk < 2; ++chunk) {
        __syncthreads();   // previous chunk's readers done
        // ---- B fill: fragment-order smem, hi and lo planes ----
        // float idx = ks*2048 + n*8 + j*2 + h ; value = w[chunk*256+n][ks*8+j+4h]
        float* bhi = (float*)(smem + OFF_B);
        float* blo = bhi + 16384;
        for (int e = tid; e < 16384; e += 256) {
            const int ks = e >> 11;
            const int n  = (e >> 3) & 255;
            const int j  = (e >> 1) & 3;
            const int h  = e & 1;
            const int k  = ks * 8 + j + (h << 2);
            const float v = w[(chunk * 256 + n) * C + k];
            const uint32_t hi = f2tf32(v);
            bhi[e] = __uint_as_float(hi);
            blo[e] = v - __uint_as_float(hi);
        }
        __syncthreads();

        #pragma unroll 1
        for (int nt2 = 0; nt2 < 16; ++nt2) {
            float acc00[4] = {0.f, 0.f, 0.f, 0.f};   // Mt0, ntile even
            float acc01[4] = {0.f, 0.f, 0.f, 0.f};   // Mt0, ntile odd
            float acc10[4] = {0.f, 0.f, 0.f, 0.f};   // Mt1, ntile even
            float acc11[4] = {0.f, 0.f, 0.f, 0.f};   // Mt1, ntile odd
            const uint32_t ntoff = (uint32_t)(nt2 * 512) + loff;

            #define PASS_BODY(AARR0, AARR1, PLANE_OFF)                          \
                {                                                               \
                    const uint32_t pb = bbase + (PLANE_OFF) + ntoff;            \
                    _Pragma("unroll")                                           \
                    for (int ks = 0; ks < 8; ++ks) {                            \
                        uint32_t b00, b01, b10, b11;                            \
                        LDS64(b00, b01, pb + ks * 8192);                        \
                        LDS64(b10, b11, pb + ks * 8192 + 256);                  \
                        MMA_TF32(acc00, AARR0[ks], b00, b01);                   \
                        MMA_TF32(acc01, AARR0[ks], b10, b11);                   \
                        MMA_TF32(acc10, AARR1[ks], b00, b01);                   \
                        MMA_TF32(acc11, AARR1[ks], b10, b11);                   \
                    }                                                           \
                }
            PASS_BODY(Ahi0, Ahi1, 0u)        // hi * hi
            PASS_BODY(Ahi0, Ahi1, 65536u)    // hi * lo
            PASS_BODY(Alo0, Alo1, 0u)        // lo * hi
            #undef PASS_BODY

            // ---- finalize: score = wsq - 2*dot, fold into running argmin ----
            // acc[0]=row(l/4),col j0 ; acc[1]=col j0+1 ; acc[2]=row+8 ; acc[3]
            #define FIN(ACC, NT, BSA, BIA, BSB, BIB)                            \
                {                                                               \
                    const int cb = chunk * 256 + (nt2 * 2 + (NT)) * 8 + ((l & 3) << 1); \
                    const float wq0 = wsqs[cb], wq1 = wsqs[cb + 1];             \
                    float sc;                                                   \
                    sc = fmaf(-2.f, ACC[0], wq0);                               \
                    if (sc < BSA) { BSA = sc; BIA = cb; }                       \
                    sc = fmaf(-2.f, ACC[1], wq1);                               \
                    if (sc < BSA) { BSA = sc; BIA = cb + 1; }                   \
                    sc = fmaf(-2.f, ACC[2], wq0);                               \
                    if (sc < BSB) { BSB = sc; BIB = cb; }                       \
                    sc = fmaf(-2.f, ACC[3], wq1);                               \
                    if (sc < BSB) { BSB = sc; BIB = cb + 1; }                   \
                }
            FIN(acc00, 0, best0, bidx0, best1, bidx1)
            FIN(acc01, 1, best0, bidx0, best1, bidx1)
            FIN(acc10, 0, best2, bidx2, best3, bidx3)
            FIN(acc11, 1, best2, bidx2, best3, bidx3)
            #undef FIN
        }
    }

    // ---- cross-lane argmin within quads (cols split across l%4) ----
    // slot s: position = wbase + l/4 + (s&1)*8 + (s>>1)*16
    #define QREDUCE(BS, BI, SLOT)                                               \
        {                                                                       \
            float v = BS; int vi = BI;                                          \
            _Pragma("unroll")                                                   \
            for (int off = 1; off <= 2; off <<= 1) {                            \
                const float ov = __shfl_xor_sync(0xffffffffu, v, off);          \
                const int  ovi = __shfl_xor_sync(0xffffffffu, vi, off);         \
                if (ov < v || (ov == v && ovi < vi)) { v = ov; vi = ovi; }      \
            }                                                                   \
            if ((l & 3) == 0)                                                   \
                idxb[wbase + (l >> 2) + (((SLOT) & 1) << 3) + (((SLOT) >> 1) << 4)] = vi; \
        }
    QREDUCE(best0, bidx0, 0)
    QREDUCE(best1, bidx1, 1)
    QREDUCE(best2, bidx2, 2)
    QREDUCE(best3, bidx3, 3)
    #undef QREDUCE
    __syncthreads();

    // ---- epilogue: per-thread position, q = fl(fl(w-x)+x), loss ----
    const int bestj = idxb[tid];
    out_idx[p0 + tid] = (float)bestj;

    float acc = 0.f;
    const float4* wrow = (const float4*)(w + bestj * C);
    float* qb = out_q + (size_t)b * C * S + s0 + tid;
    #pragma unroll 4
    for (int c4 = 0; c4 < 16; ++c4) {
        const float4 q4 = wrow[c4];
        const float qv[4] = {q4.x, q4.y, q4.z, q4.w};
        #pragma unroll
        for (int u = 0; u < 4; ++u) {
            const int c = c4 * 4 + u;
            const float xv = xs[tid * 68 + c];
            const float d = qv[u] - xv;
            qb[(size_t)c * S] = d + xv;
            acc = fmaf(d, d, acc);
        }
    }

    redb[tid] = acc;
    __syncthreads();
    #pragma unroll
    for (int off = 128; off > 0; off >>= 1) {
        if (tid < off) redb[tid] += redb[tid + off];
        __syncthreads();
    }
    if (tid == 0) g_partials[blockIdx.x] = redb[0];
}

// ---------------------------------------------------------------------------
__global__ void __launch_bounds__(256) loss_final_kernel(
    float* __restrict__ out_loss, int nblocks, float inv_n)
{
    __shared__ float red[256];
    const int tid = threadIdx.x;
    float a = 0.f;
    for (int i = tid; i < nblocks; i += 256) a += g_partials[i];
    red[tid] = a;
    __syncthreads();
    #pragma unroll
    for (int off = 128; off > 0; off >>= 1) {
        if (tid < off) red[tid] += red[tid + off];
        __syncthreads();
    }
    if (tid == 0) out_loss[0] = 0.25f * red[0] * inv_n;
}

// ---------------------------------------------------------------------------
extern "C" void kernel_launch(void* const* d_in, const int* in_sizes, int n_in,
                              void* d_out, int out_size)
{
    const float* x = (const float*)d_in[0];
    const float* w = (const float*)d_in[1];
    float* out = (float*)d_out;

    const int n_x  = in_sizes[0];   // 8388608
    const int npos = n_x / C;       // 131072

    float* out_q    = out;
    float* out_idx  = out + n_x;
    float* out_loss = out + n_x + npos;

    cudaFuncSetAttribute(vq_hmma_kernel,
                         cudaFuncAttributeMaxDynamicSharedMemorySize, SMEM_TOTAL);

    const int blocks = npos / 256;   // 512
    vq_hmma_kernel<<<blocks, 256, SMEM_TOTAL>>>(x, w, out_q, out_idx);
    loss_final_kernel<<<1, 256>>>(out_loss, blocks, 1.0f / (float)n_x);
}